// round 14
// baseline (speedup 1.0000x reference)
#include <cuda_runtime.h>
#include <cuda_bf16.h>

// Problem constants
#define Bz 4
#define Nz 128
#define Mz 128
#define Dz 256
#define BDz 1024

#define NDC 8                    // d-chunks (32 d each)
#define TSZ (Bz * Nz * Dz)       // 131072 elems per T partial
#define SSZ (Bz * Nz * Mz)       // 65536 elems (S)
#define KSPLIT 4                 // e-chunk split in the tail
#define NBLK 256                 // total blocks (single wave on 148 SMs)
#define NTAIL 128                // tail tiles (tickets NBLK-NTAIL .. NBLK-1)

// Scratch in device globals (no allocation allowed). Counters are reset by
// the last epilogue winner each run => graph-replay safe.
__device__ float g_Tp[NDC * TSZ];          // T partials over 8 d-chunks (4 MB)
__device__ float g_Sp[KSPLIT * SSZ];       // S partials over 4 e-chunks
__device__ int   g_done;                   // producer completions (target 256)
__device__ int   g_cnt3[32];               // S-group tickets (b4 x nt4 x mt2)
__device__ int   g_epi;                    // epilogue winners (target 32)

__device__ __forceinline__ int ld_vol(const int* p) { return *(volatile const int*)p; }

// ---------------------------------------------------------------------------
// Single kernel. 256 blocks, 256 threads.
//  Producer phase (all blocks): round-13 k1T body:
//    ph1: Aw[32x8] tile = A-slab (1 MB) dot W      (268 MB streamed once)
//    ph2: Tp[dchunk][r, e0:e0+8] = X[:,dchunk] @ Aw (X is L2-resident)
//  Ticketed tail (last 128 finishers): after done==256,
//    Sp[kse][b, n0:n0+32, m0:m0+64] = Tsum @ Y^T   (T summed over 8 d-partials,
//    fixed order), then per-group sLast sums 4 Sp + bias -> S (fixed order).
// ---------------------------------------------------------------------------
__global__ __launch_bounds__(256) void k_all(const float* __restrict__ A,
                                             const float* __restrict__ W,
                                             const float* __restrict__ X,
                                             const float* __restrict__ Y,
                                             const float* __restrict__ bias,
                                             float* __restrict__ S) {
    __shared__ float4 sW[BDz / 4];                 // 4 KB
    __shared__ __align__(16) float sAw[32][8];     // 1 KB
    __shared__ __align__(16) float sT[32][65];     // 8.3 KB (tail)
    __shared__ __align__(16) float sY[64][65];     // 16.6 KB (tail)
    __shared__ int sTicket;
    __shared__ int sLast;

    int tid = threadIdx.x;
    int bid = blockIdx.x;

    int etile  = bid >> 3;          // 0..31
    int dchunk = bid & 7;           // 0..7
    int e0 = etile * 8;
    int d0 = dchunk * 32;

    sW[tid] = reinterpret_cast<const float4*>(W)[tid];
    __syncthreads();

    int warp = tid >> 5;
    int lane = tid & 31;

    // ---- Phase 1: 256 (d,e) rows, 8 warps x 32 iterations ----
#pragma unroll 4
    for (int it = 0; it < 32; it++) {
        int row = it * 8 + warp;              // 0..255 = dl*8 + el
        int dl = row >> 3, el = row & 7;
        const float4* Arow = reinterpret_cast<const float4*>(A)
                           + ((long)(d0 + dl) * Dz + (e0 + el)) * (BDz / 4);
        float acc = 0.0f;
#pragma unroll
        for (int i = 0; i < 8; i++) {
            float4 a = Arow[i * 32 + lane];
            float4 w = sW[i * 32 + lane];
            acc += a.x * w.x + a.y * w.y + a.z * w.z + a.w * w.w;
        }
#pragma unroll
        for (int off = 16; off; off >>= 1)
            acc += __shfl_xor_sync(0xffffffffu, acc, off);
        if (lane == 0) sAw[dl][el] = acc;
    }
    __syncthreads();

    // ---- Phase 2: Tp partial (verbatim round-13) ----
    {
        int eh = tid & 1;
        int g  = tid >> 1;
        const float4* X4 = reinterpret_cast<const float4*>(X);
        const float4* AwQ = reinterpret_cast<const float4*>(&sAw[0][0]) + eh;

#pragma unroll
        for (int i = 0; i < 4; i++) {
            int r = g * 4 + i;                // flattened (b,n) row, 0..511
            float4 acc = make_float4(0.f, 0.f, 0.f, 0.f);
#pragma unroll
            for (int d4 = 0; d4 < 8; d4++) {
                float4 xv = X4[(long)r * (Dz / 4) + dchunk * 8 + d4];
                float4 w0 = AwQ[(d4 * 4 + 0) * 2];
                float4 w1 = AwQ[(d4 * 4 + 1) * 2];
                float4 w2 = AwQ[(d4 * 4 + 2) * 2];
                float4 w3 = AwQ[(d4 * 4 + 3) * 2];
                acc.x += xv.x * w0.x + xv.y * w1.x + xv.z * w2.x + xv.w * w3.x;
                acc.y += xv.x * w0.y + xv.y * w1.y + xv.z * w2.y + xv.w * w3.y;
                acc.z += xv.x * w0.z + xv.y * w1.z + xv.z * w2.z + xv.w * w3.z;
                acc.w += xv.x * w0.w + xv.y * w1.w + xv.z * w2.w + xv.w * w3.w;
            }
            reinterpret_cast<float4*>(g_Tp)[((long)dchunk * 512 + r) * (Dz / 4)
                                            + (e0 >> 2) + eh] = acc;
        }
    }

    // ---- draw finish-order ticket ----
    __threadfence();
    __syncthreads();
    if (tid == 0) sTicket = atomicAdd(&g_done, 1);    // 0..255
    __syncthreads();
    int ticket = sTicket;
    if (ticket < NBLK - NTAIL) return;                // first 128 finishers exit

    // ---- wait for all producers (we are among the last 128, already warm) ----
    if (tid == 0) {
        while (ld_vol(&g_done) < NBLK) __nanosleep(64);
        __threadfence();
    }
    __syncthreads();

    // ---- tail tile: t in [0,128): 32n x 64m x e-chunk(64) ----
    {
        int t  = ticket - (NBLK - NTAIL);
        int mt = t & 1;                  // m-tile of 64
        int nt = (t >> 1) & 3;           // n-tile of 32
        int z  = t >> 3;                 // 0..15
        int b  = z >> 2;
        int kse = z & 3;
        int m0 = mt * 64;
        int n0 = nt * 32;
        int kc = kse * 64;
        int gid = (b * 4 + nt) * 2 + mt; // 0..31

        int tx = tid & 15;               // m group
        int ty = tid >> 4;               // n group

        long tb = (long)b * Nz * Dz;
        const float* Yb = Y + (long)b * Mz * Dz;

        // sT: 32x64, sum of 8 d-partials in fixed order
#pragma unroll
        for (int it2 = 0; it2 < 2; it2++) {
            int lin = tid + it2 * 256;   // 0..511
            int row = lin >> 4;          // 0..31
            int c4  = (lin & 15) << 2;
            long base = tb + (long)(n0 + row) * Dz + kc + c4;
            float4 s = *reinterpret_cast<const float4*>(&g_Tp[0 * TSZ + base]);
#pragma unroll
            for (int dc = 1; dc < NDC; dc++) {
                float4 tv = *reinterpret_cast<const float4*>(&g_Tp[(long)dc * TSZ + base]);
                s.x += tv.x; s.y += tv.y; s.z += tv.z; s.w += tv.w;
            }
            sT[row][c4 + 0] = s.x; sT[row][c4 + 1] = s.y;
            sT[row][c4 + 2] = s.z; sT[row][c4 + 3] = s.w;
        }
        // sY: 64x64
#pragma unroll
        for (int it2 = 0; it2 < 4; it2++) {
            int lin = tid + it2 * 256;
            int row = lin >> 4;
            int c4  = (lin & 15) << 2;
            float4 yv = *reinterpret_cast<const float4*>(&Yb[(long)(m0 + row) * Dz + kc + c4]);
            sY[row][c4 + 0] = yv.x; sY[row][c4 + 1] = yv.y;
            sY[row][c4 + 2] = yv.z; sY[row][c4 + 3] = yv.w;
        }
        __syncthreads();

        float acc[2][4] = {};
#pragma unroll 16
        for (int e = 0; e < 64; e++) {
            float tv[2], yv[4];
#pragma unroll
            for (int i = 0; i < 2; i++) tv[i] = sT[ty + 16 * i][e];
#pragma unroll
            for (int j = 0; j < 4; j++) yv[j] = sY[tx + 16 * j][e];
#pragma unroll
            for (int i = 0; i < 2; i++)
#pragma unroll
                for (int j = 0; j < 4; j++)
                    acc[i][j] += tv[i] * yv[j];
        }

        long sbase = (long)b * Nz * Mz;
        float* out = g_Sp + (long)kse * SSZ + sbase;
#pragma unroll
        for (int i = 0; i < 2; i++)
#pragma unroll
            for (int j = 0; j < 4; j++)
                out[(n0 + ty + 16 * i) * Mz + m0 + tx + 16 * j] = acc[i][j];

        // ---- per-group deterministic split-K epilogue ----
        __threadfence();
        __syncthreads();
        if (tid == 0) sLast = (atomicAdd(&g_cnt3[gid], 1) == KSPLIT - 1);
        __syncthreads();
        if (sLast) {
            float bv = bias[0];
#pragma unroll
            for (int it2 = 0; it2 < 2; it2++) {
                int lin = tid + it2 * 256;    // 512 float4 slots (32 x 64 region)
                int row = lin >> 4;           // 0..31
                int c4  = (lin & 15) << 2;
                long p = sbase + (long)(n0 + row) * Mz + m0 + c4;
                float4 a0 = *reinterpret_cast<const float4*>(&g_Sp[0 * SSZ + p]);
                float4 a1 = *reinterpret_cast<const float4*>(&g_Sp[1 * SSZ + p]);
                float4 a2 = *reinterpret_cast<const float4*>(&g_Sp[2 * SSZ + p]);
                float4 a3 = *reinterpret_cast<const float4*>(&g_Sp[3 * SSZ + p]);
                float4 r;
                r.x = a0.x + a1.x + a2.x + a3.x + bv;
                r.y = a0.y + a1.y + a2.y + a3.y + bv;
                r.z = a0.z + a1.z + a2.z + a3.z + bv;
                r.w = a0.w + a1.w + a2.w + a3.w + bv;
                *reinterpret_cast<float4*>(&S[p]) = r;
            }
            // last of the 32 winners resets counters for graph replay
            __threadfence();
            if (tid == 0) {
                int w = atomicAdd(&g_epi, 1);
                if (w == 31) {
                    for (int i = 0; i < 32; i++) g_cnt3[i] = 0;
                    g_done = 0;
                    g_epi = 0;
                }
            }
        }
    }
}

// ---------------------------------------------------------------------------
// Launch: inputs in order X, Y, A, W, b — ONE launch.
// ---------------------------------------------------------------------------
extern "C" void kernel_launch(void* const* d_in, const int* in_sizes, int n_in,
                              void* d_out, int out_size) {
    const float* X = (const float*)d_in[0];  // [4,128,256]
    const float* Y = (const float*)d_in[1];  // [4,128,256]
    const float* A = (const float*)d_in[2];  // [256,256,1024]
    const float* W = (const float*)d_in[3];  // [1,1024]
    const float* b = (const float*)d_in[4];  // [1]
    float* S = (float*)d_out;                // [4,128,128]

    k_all<<<NBLK, 256>>>(A, W, X, Y, b, S);
}